// round 2
// baseline (speedup 1.0000x reference)
#include <cuda_runtime.h>

// Fixed problem shapes
#define BSZ  4
#define TT   1024
#define DDIM 512
#define HH   8
#define DH   64
#define MROWS (BSZ*TT)   // 4096
#define NBH   (BSZ*HH)   // 32
#define INV_TAU 10.0f

// Scratch (device globals: allocation-free)
__device__ __align__(128) float g_qkv[3][MROWS][DDIM];   // 25 MB: q,k,v post-softmax
__device__ __align__(128) float g_S[NBH][TT][TT];        // 134 MB: scores -> scan -> probs
__device__ __align__(128) float g_O[NBH][TT][DH];        // 8 MB: attention output

// ---------------------------------------------------------------------------
// K1: QKV projections. 128x128 tile, BK=8, 8x8 per thread, 256 threads.
// grid (4, 32, 3)
// ---------------------------------------------------------------------------
__global__ __launch_bounds__(256) void k_qkv(const float* __restrict__ X,
                                             const float* __restrict__ Wq,
                                             const float* __restrict__ Wk,
                                             const float* __restrict__ Wv) {
    const float* W = (blockIdx.z == 0) ? Wq : ((blockIdx.z == 1) ? Wk : Wv);
    float* Out = &g_qkv[blockIdx.z][0][0];
    __shared__ float As[8][128];
    __shared__ float Bs[8][128];
    int tid = threadIdx.x;
    int m0 = blockIdx.y * 128, n0 = blockIdx.x * 128;
    int arow = tid >> 1, acol = (tid & 1) * 4;
    int brow = tid >> 5, bcol = (tid & 31) * 4;
    int tx = tid & 15, ty = tid >> 4;
    float acc[8][8];
#pragma unroll
    for (int r = 0; r < 8; r++)
#pragma unroll
        for (int c = 0; c < 8; c++) acc[r][c] = 0.f;

    for (int k0 = 0; k0 < DDIM; k0 += 8) {
        float4 av = *(const float4*)&X[(m0 + arow) * DDIM + k0 + acol];
        float4 bv = *(const float4*)&W[(k0 + brow) * DDIM + n0 + bcol];
        __syncthreads();
        As[acol + 0][arow] = av.x; As[acol + 1][arow] = av.y;
        As[acol + 2][arow] = av.z; As[acol + 3][arow] = av.w;
        *(float4*)&Bs[brow][bcol] = bv;
        __syncthreads();
#pragma unroll
        for (int k = 0; k < 8; k++) {
            float a[8], b[8];
            *(float4*)&a[0] = *(const float4*)&As[k][ty * 8];
            *(float4*)&a[4] = *(const float4*)&As[k][ty * 8 + 4];
            *(float4*)&b[0] = *(const float4*)&Bs[k][tx * 8];
            *(float4*)&b[4] = *(const float4*)&Bs[k][tx * 8 + 4];
#pragma unroll
            for (int r = 0; r < 8; r++)
#pragma unroll
                for (int c = 0; c < 8; c++) acc[r][c] += a[r] * b[c];
        }
    }
#pragma unroll
    for (int r = 0; r < 8; r++) {
        int row = m0 + ty * 8 + r;
        *(float4*)&Out[row * DDIM + n0 + tx * 8]     = *(float4*)&acc[r][0];
        *(float4*)&Out[row * DDIM + n0 + tx * 8 + 4] = *(float4*)&acc[r][4];
    }
}

// ---------------------------------------------------------------------------
// K2: per-head softmax(x/tau) over 64 elems, in place on g_qkv.
// One warp per row of 64. rows = 3*4096*8 = 98304, grid 12288 x 256.
// ---------------------------------------------------------------------------
__global__ __launch_bounds__(256) void k_sm64() {
    int wrp = (blockIdx.x << 3) + (threadIdx.x >> 5);
    int lane = threadIdx.x & 31;
    float* p = ((float*)g_qkv) + (size_t)wrp * 64;
    float2 v = *(float2*)&p[lane * 2];
    float mx = fmaxf(v.x, v.y);
#pragma unroll
    for (int o = 16; o > 0; o >>= 1) mx = fmaxf(mx, __shfl_xor_sync(0xffffffffu, mx, o));
    float e0 = __expf((v.x - mx) * INV_TAU);
    float e1 = __expf((v.y - mx) * INV_TAU);
    float s = e0 + e1;
#pragma unroll
    for (int o = 16; o > 0; o >>= 1) s += __shfl_xor_sync(0xffffffffu, s, o);
    float inv = 1.f / s;
    float2 r; r.x = e0 * inv; r.y = e1 * inv;
    *(float2*)&p[lane * 2] = r;
}

// ---------------------------------------------------------------------------
// K3: S[bh][i][j] = q_sm[i]·k_sm[j], causal tiles only. 64x64 tile, K=64.
// grid (16, 16, 32), block 256, 4x4 per thread.
// ---------------------------------------------------------------------------
__global__ __launch_bounds__(256) void k_score() {
    int jt = blockIdx.x, it = blockIdx.y, bh = blockIdx.z;
    if (jt > it) return;
    int b = bh >> 3, h = bh & 7;
    const float* Q  = &g_qkv[0][b * TT][h * DH];
    const float* Kp = &g_qkv[1][b * TT][h * DH];
    __shared__ float Qs[DH][68];
    __shared__ float Ks[DH][68];
    int tid = threadIdx.x;
    int lrow = tid >> 4, lcol = (tid & 15) * 4;
#pragma unroll
    for (int l = 0; l < 4; l++) {
        int row = lrow + l * 16;
        float4 q4 = *(const float4*)&Q[(it * 64 + row) * DDIM + lcol];
        float4 k4 = *(const float4*)&Kp[(jt * 64 + row) * DDIM + lcol];
        Qs[lcol + 0][row] = q4.x; Qs[lcol + 1][row] = q4.y;
        Qs[lcol + 2][row] = q4.z; Qs[lcol + 3][row] = q4.w;
        Ks[lcol + 0][row] = k4.x; Ks[lcol + 1][row] = k4.y;
        Ks[lcol + 2][row] = k4.z; Ks[lcol + 3][row] = k4.w;
    }
    __syncthreads();
    int tx = tid & 15, ty = tid >> 4;
    float acc[4][4];
#pragma unroll
    for (int r = 0; r < 4; r++)
#pragma unroll
        for (int c = 0; c < 4; c++) acc[r][c] = 0.f;
#pragma unroll 8
    for (int k = 0; k < 64; k++) {
        float4 a4 = *(const float4*)&Qs[k][ty * 4];
        float4 b4 = *(const float4*)&Ks[k][tx * 4];
        float a[4] = {a4.x, a4.y, a4.z, a4.w};
        float bb[4] = {b4.x, b4.y, b4.z, b4.w};
#pragma unroll
        for (int r = 0; r < 4; r++)
#pragma unroll
            for (int c = 0; c < 4; c++) acc[r][c] += a[r] * bb[c];
    }
    float* Sp = &g_S[bh][0][0];
#pragma unroll
    for (int r = 0; r < 4; r++) {
        float4 o4 = {acc[r][0], acc[r][1], acc[r][2], acc[r][3]};
        *(float4*)&Sp[(it * 64 + ty * 4 + r) * TT + jt * 64 + tx * 4] = o4;
    }
}

// ---------------------------------------------------------------------------
// K4: per-subdiagonal scan, in place on g_S. Thread t owns diagonal
// d = bx*256 + t; at row i it touches column i-d (reversed-coalesced).
// 8-deep register prefetch pipeline to hide DRAM latency.
// grid (4, 32), block 256.
// ---------------------------------------------------------------------------
__global__ __launch_bounds__(256) void k_scan() {
    int bh = blockIdx.y;
    int dbase = blockIdx.x * 256;
    int t = threadIdx.x;
    int d = dbase + t;
    float* Sp = &g_S[bh][0][0];
    const int PF = 8;
    float buf[PF];
    float s = 0.f, m = 0.f;
#pragma unroll
    for (int p = 0; p < PF; p++) {
        int i = dbase + p;
        int j = i - d;
        buf[p] = (j >= 0 && i < TT) ? Sp[i * TT + j] : 0.f;
    }
    for (int i = dbase; i < TT; i++) {
        float a = buf[0];
#pragma unroll
        for (int p = 0; p < PF - 1; p++) buf[p] = buf[p + 1];
        int ip = i + PF, jp = ip - d;
        buf[PF - 1] = (ip < TT && jp >= 0) ? Sp[ip * TT + jp] : 0.f;
        if (i >= d) {
            s += a;
            m = fmaxf(m, s * (1.f - a));
            Sp[i * TT + (i - d)] = s - m;
        }
    }
}

// ---------------------------------------------------------------------------
// K5: causal softmax of (scan + j/(i+1))/tau over j<=i, in place.
// One block (256 thr) per (bh, i). grid (1024, 32).
// ---------------------------------------------------------------------------
__global__ __launch_bounds__(256) void k_attnsm() {
    int i = blockIdx.x, bh = blockIdx.y;
    float* row = &g_S[bh][i][0];
    int tid = threadIdx.x;
    int n = i + 1;
    float inv_i = 1.f / (float)n;
    __shared__ float red[8];

    float mx = -1e30f;
    for (int j = tid; j < n; j += 256) mx = fmaxf(mx, row[j] + (float)j * inv_i);
#pragma unroll
    for (int o = 16; o > 0; o >>= 1) mx = fmaxf(mx, __shfl_xor_sync(0xffffffffu, mx, o));
    if ((tid & 31) == 0) red[tid >> 5] = mx;
    __syncthreads();
    if (tid < 32) {
        float v = (tid < 8) ? red[tid] : -1e30f;
#pragma unroll
        for (int o = 4; o > 0; o >>= 1) v = fmaxf(v, __shfl_xor_sync(0xffffffffu, v, o));
        if (tid == 0) red[0] = v;
    }
    __syncthreads();
    float bmax = red[0];
    __syncthreads();

    float ssum = 0.f;
    for (int j = tid; j < n; j += 256) {
        float e = __expf((row[j] + (float)j * inv_i - bmax) * INV_TAU);
        row[j] = e;
        ssum += e;
    }
#pragma unroll
    for (int o = 16; o > 0; o >>= 1) ssum += __shfl_xor_sync(0xffffffffu, ssum, o);
    if ((tid & 31) == 0) red[tid >> 5] = ssum;
    __syncthreads();
    if (tid < 32) {
        float v = (tid < 8) ? red[tid] : 0.f;
#pragma unroll
        for (int o = 4; o > 0; o >>= 1) v += __shfl_xor_sync(0xffffffffu, v, o);
        if (tid == 0) red[0] = v;
    }
    __syncthreads();
    float inv = 1.f / red[0];
    for (int j = tid; j < n; j += 256) row[j] *= inv;
}

// ---------------------------------------------------------------------------
// K6: O = P @ V_sm per (b,h), causal (mask applied at P load in diag tile).
// 64 rows x 64 cols (Dh), BK=16. grid (16, 32), block 256.
// ---------------------------------------------------------------------------
__global__ __launch_bounds__(256) void k_pv() {
    int it = blockIdx.x, bh = blockIdx.y;
    int b = bh >> 3, h = bh & 7;
    const float* P = &g_S[bh][0][0];
    const float* V = &g_qkv[2][b * TT][h * DH];
    __shared__ float Ps[16][68];
    __shared__ float Vs[16][68];
    int tid = threadIdx.x;
    int prow = tid >> 2, pcol = (tid & 3) * 4;
    int vrow = tid >> 4, vcol = (tid & 15) * 4;
    int tx = tid & 15, ty = tid >> 4;
    float acc[4][4];
#pragma unroll
    for (int r = 0; r < 4; r++)
#pragma unroll
        for (int c = 0; c < 4; c++) acc[r][c] = 0.f;
    int i0 = it * 64;
    int kend = i0 + 64;
    for (int j0 = 0; j0 < kend; j0 += 16) {
        int i_g = i0 + prow;
        float4 p4 = *(const float4*)&P[i_g * TT + j0 + pcol];
        if (j0 + pcol + 0 > i_g) p4.x = 0.f;
        if (j0 + pcol + 1 > i_g) p4.y = 0.f;
        if (j0 + pcol + 2 > i_g) p4.z = 0.f;
        if (j0 + pcol + 3 > i_g) p4.w = 0.f;
        float4 v4 = *(const float4*)&V[(j0 + vrow) * DDIM + vcol];
        __syncthreads();
        Ps[pcol + 0][prow] = p4.x; Ps[pcol + 1][prow] = p4.y;
        Ps[pcol + 2][prow] = p4.z; Ps[pcol + 3][prow] = p4.w;
        *(float4*)&Vs[vrow][vcol] = v4;
        __syncthreads();
#pragma unroll
        for (int k = 0; k < 16; k++) {
            float4 a4 = *(const float4*)&Ps[k][ty * 4];
            float4 b4 = *(const float4*)&Vs[k][tx * 4];
            float a[4] = {a4.x, a4.y, a4.z, a4.w};
            float bb[4] = {b4.x, b4.y, b4.z, b4.w};
#pragma unroll
            for (int r = 0; r < 4; r++)
#pragma unroll
                for (int c = 0; c < 4; c++) acc[r][c] += a[r] * bb[c];
        }
    }
#pragma unroll
    for (int r = 0; r < 4; r++) {
        float4 o4 = {acc[r][0], acc[r][1], acc[r][2], acc[r][3]};
        *(float4*)&g_O[bh][i0 + ty * 4 + r][tx * 4] = o4;
    }
}

// ---------------------------------------------------------------------------
// K7: out[b,t,h*64+e] = sum_d O[bh][t][d] * wo[h*64+d][e]. K=64, N=64.
// grid (16, 32), block 256.
// ---------------------------------------------------------------------------
__global__ __launch_bounds__(256) void k_out(const float* __restrict__ wo,
                                             float* __restrict__ out) {
    int it = blockIdx.x, bh = blockIdx.y;
    int b = bh >> 3, h = bh & 7;
    __shared__ float Os[DH][68];
    __shared__ float Ws[DH][68];
    int tid = threadIdx.x;
    int lrow = tid >> 4, lcol = (tid & 15) * 4;
#pragma unroll
    for (int l = 0; l < 4; l++) {
        int row = lrow + l * 16;
        float4 o4 = *(const float4*)&g_O[bh][it * 64 + row][lcol];
        Os[lcol + 0][row] = o4.x; Os[lcol + 1][row] = o4.y;
        Os[lcol + 2][row] = o4.z; Os[lcol + 3][row] = o4.w;
        float4 w4 = *(const float4*)&wo[(h * 64 + row) * 64 + lcol];
        *(float4*)&Ws[row][lcol] = w4;
    }
    __syncthreads();
    int tx = tid & 15, ty = tid >> 4;
    float acc[4][4];
#pragma unroll
    for (int r = 0; r < 4; r++)
#pragma unroll
        for (int c = 0; c < 4; c++) acc[r][c] = 0.f;
#pragma unroll 8
    for (int k = 0; k < 64; k++) {
        float4 a4 = *(const float4*)&Os[k][ty * 4];
        float4 b4 = *(const float4*)&Ws[k][tx * 4];
        float a[4] = {a4.x, a4.y, a4.z, a4.w};
        float bb[4] = {b4.x, b4.y, b4.z, b4.w};
#pragma unroll
        for (int r = 0; r < 4; r++)
#pragma unroll
            for (int c = 0; c < 4; c++) acc[r][c] += a[r] * bb[c];
    }
#pragma unroll
    for (int r = 0; r < 4; r++) {
        int t = it * 64 + ty * 4 + r;
        float4 o4 = {acc[r][0], acc[r][1], acc[r][2], acc[r][3]};
        *(float4*)&out[(b * TT + t) * DDIM + h * 64 + tx * 4] = o4;
    }
}

// ---------------------------------------------------------------------------
extern "C" void kernel_launch(void* const* d_in, const int* in_sizes, int n_in,
                              void* d_out, int out_size) {
    const float* x  = (const float*)d_in[0];
    const float* wq = (const float*)d_in[1];
    const float* wk = (const float*)d_in[2];
    const float* wv = (const float*)d_in[3];
    const float* wo = (const float*)d_in[4];
    float* out = (float*)d_out;

    k_qkv<<<dim3(4, 32, 3), 256>>>(x, wq, wk, wv);
    k_sm64<<<12288, 256>>>();
    k_score<<<dim3(16, 16, 32), 256>>>();
    k_scan<<<dim3(4, 32), 256>>>();
    k_attnsm<<<dim3(1024, 32), 256>>>();
    k_pv<<<dim3(16, 32), 256>>>();
    k_out<<<dim3(16, 32), 256>>>(wo, out);
}

// round 4
// speedup vs baseline: 1.3209x; 1.3209x over previous
#include <cuda_runtime.h>

// Fixed problem shapes
#define BSZ  4
#define TT   1024
#define DDIM 512
#define HH   8
#define DH   64
#define MROWS (BSZ*TT)   // 4096
#define NBH   (BSZ*HH)   // 32
#define INV_TAU 10.0f

// Scratch (device globals: allocation-free)
__device__ __align__(128) float g_qkv[3][MROWS][DDIM];   // 25 MB: q,k,v post-softmax
__device__ __align__(128) float g_S[NBH][TT][TT];        // 134 MB: scores -> scan
__device__ __align__(128) float g_O[NBH][TT][DH];        // 8 MB: attention output

// ---------------------------------------------------------------------------
// K1: QKV projections. 128x128 tile, BK=8, 8x8 per thread, 256 threads.
// grid (4, 32, 3)
// ---------------------------------------------------------------------------
__global__ __launch_bounds__(256) void k_qkv(const float* __restrict__ X,
                                             const float* __restrict__ Wq,
                                             const float* __restrict__ Wk,
                                             const float* __restrict__ Wv) {
    const float* W = (blockIdx.z == 0) ? Wq : ((blockIdx.z == 1) ? Wk : Wv);
    float* Out = &g_qkv[blockIdx.z][0][0];
    __shared__ float As[8][128];
    __shared__ float Bs[8][128];
    int tid = threadIdx.x;
    int m0 = blockIdx.y * 128, n0 = blockIdx.x * 128;
    int arow = tid >> 1, acol = (tid & 1) * 4;
    int brow = tid >> 5, bcol = (tid & 31) * 4;
    int tx = tid & 15, ty = tid >> 4;
    float acc[8][8];
#pragma unroll
    for (int r = 0; r < 8; r++)
#pragma unroll
        for (int c = 0; c < 8; c++) acc[r][c] = 0.f;

    for (int k0 = 0; k0 < DDIM; k0 += 8) {
        float4 av = *(const float4*)&X[(m0 + arow) * DDIM + k0 + acol];
        float4 bv = *(const float4*)&W[(k0 + brow) * DDIM + n0 + bcol];
        __syncthreads();
        As[acol + 0][arow] = av.x; As[acol + 1][arow] = av.y;
        As[acol + 2][arow] = av.z; As[acol + 3][arow] = av.w;
        *(float4*)&Bs[brow][bcol] = bv;
        __syncthreads();
#pragma unroll
        for (int k = 0; k < 8; k++) {
            float a[8], b[8];
            *(float4*)&a[0] = *(const float4*)&As[k][ty * 8];
            *(float4*)&a[4] = *(const float4*)&As[k][ty * 8 + 4];
            *(float4*)&b[0] = *(const float4*)&Bs[k][tx * 8];
            *(float4*)&b[4] = *(const float4*)&Bs[k][tx * 8 + 4];
#pragma unroll
            for (int r = 0; r < 8; r++)
#pragma unroll
                for (int c = 0; c < 8; c++) acc[r][c] += a[r] * b[c];
        }
    }
#pragma unroll
    for (int r = 0; r < 8; r++) {
        int row = m0 + ty * 8 + r;
        *(float4*)&Out[row * DDIM + n0 + tx * 8]     = *(float4*)&acc[r][0];
        *(float4*)&Out[row * DDIM + n0 + tx * 8 + 4] = *(float4*)&acc[r][4];
    }
}

// ---------------------------------------------------------------------------
// K2: per-head softmax(x/tau) over 64 elems, in place on g_qkv.
// ---------------------------------------------------------------------------
__global__ __launch_bounds__(256) void k_sm64() {
    int wrp = (blockIdx.x << 3) + (threadIdx.x >> 5);
    int lane = threadIdx.x & 31;
    float* p = ((float*)g_qkv) + (size_t)wrp * 64;
    float2 v = *(float2*)&p[lane * 2];
    float mx = fmaxf(v.x, v.y);
#pragma unroll
    for (int o = 16; o > 0; o >>= 1) mx = fmaxf(mx, __shfl_xor_sync(0xffffffffu, mx, o));
    float e0 = __expf((v.x - mx) * INV_TAU);
    float e1 = __expf((v.y - mx) * INV_TAU);
    float s = e0 + e1;
#pragma unroll
    for (int o = 16; o > 0; o >>= 1) s += __shfl_xor_sync(0xffffffffu, s, o);
    float inv = 1.f / s;
    float2 r; r.x = e0 * inv; r.y = e1 * inv;
    *(float2*)&p[lane * 2] = r;
}

// ---------------------------------------------------------------------------
// K3: S[bh][i][j] = q_sm[i]·k_sm[j], causal tiles only. 64x64 tile, K=64.
// grid (16, 16, 32), block 256, 4x4 per thread.
// ---------------------------------------------------------------------------
__global__ __launch_bounds__(256) void k_score() {
    int jt = blockIdx.x, it = blockIdx.y, bh = blockIdx.z;
    if (jt > it) return;
    int b = bh >> 3, h = bh & 7;
    const float* Q  = &g_qkv[0][b * TT][h * DH];
    const float* Kp = &g_qkv[1][b * TT][h * DH];
    __shared__ float Qs[DH][68];
    __shared__ float Ks[DH][68];
    int tid = threadIdx.x;
    int lrow = tid >> 4, lcol = (tid & 15) * 4;
#pragma unroll
    for (int l = 0; l < 4; l++) {
        int row = lrow + l * 16;
        float4 q4 = *(const float4*)&Q[(it * 64 + row) * DDIM + lcol];
        float4 k4 = *(const float4*)&Kp[(jt * 64 + row) * DDIM + lcol];
        Qs[lcol + 0][row] = q4.x; Qs[lcol + 1][row] = q4.y;
        Qs[lcol + 2][row] = q4.z; Qs[lcol + 3][row] = q4.w;
        Ks[lcol + 0][row] = k4.x; Ks[lcol + 1][row] = k4.y;
        Ks[lcol + 2][row] = k4.z; Ks[lcol + 3][row] = k4.w;
    }
    __syncthreads();
    int tx = tid & 15, ty = tid >> 4;
    float acc[4][4];
#pragma unroll
    for (int r = 0; r < 4; r++)
#pragma unroll
        for (int c = 0; c < 4; c++) acc[r][c] = 0.f;
#pragma unroll 8
    for (int k = 0; k < 64; k++) {
        float4 a4 = *(const float4*)&Qs[k][ty * 4];
        float4 b4 = *(const float4*)&Ks[k][tx * 4];
        float a[4] = {a4.x, a4.y, a4.z, a4.w};
        float bb[4] = {b4.x, b4.y, b4.z, b4.w};
#pragma unroll
        for (int r = 0; r < 4; r++)
#pragma unroll
            for (int c = 0; c < 4; c++) acc[r][c] += a[r] * bb[c];
    }
    float* Sp = &g_S[bh][0][0];
#pragma unroll
    for (int r = 0; r < 4; r++) {
        float4 o4 = {acc[r][0], acc[r][1], acc[r][2], acc[r][3]};
        *(float4*)&Sp[(it * 64 + ty * 4 + r) * TT + jt * 64 + tx * 4] = o4;
    }
}

// ---------------------------------------------------------------------------
// K4: per-subdiagonal scan, in place on g_S. Thread t owns diagonal d.
// A/B double-buffered 16-row blocks: loads are issued one FULL block before
// consumption -> MLP=16. grid (8, 32), block 128.
// ---------------------------------------------------------------------------
#define SPF 16
__global__ __launch_bounds__(128) void k_scan() {
    int bh = blockIdx.y;
    int dbase = blockIdx.x * 128;
    int d = dbase + threadIdx.x;
    float* Sp = &g_S[bh][0][0];
    float bufA[SPF], bufB[SPF];
    float s = 0.f, m = 0.f;
#pragma unroll
    for (int p = 0; p < SPF; p++) {
        int i = dbase + p, j = i - d;
        bufA[p] = (j >= 0) ? Sp[i * TT + j] : 0.f;
    }
    for (int ib = dbase; ib < TT; ib += 2 * SPF) {
#pragma unroll
        for (int p = 0; p < SPF; p++) {
            int i = ib + SPF + p, j = i - d;
            bufB[p] = (j >= 0) ? Sp[i * TT + j] : 0.f;
        }
#pragma unroll
        for (int p = 0; p < SPF; p++) {
            int i = ib + p;
            if (i >= d) {
                float a = bufA[p];
                s += a;
                m = fmaxf(m, s * (1.f - a));
                Sp[i * TT + (i - d)] = s - m;
            }
        }
#pragma unroll
        for (int p = 0; p < SPF; p++) {
            int i = ib + 2 * SPF + p, j = i - d;
            bufA[p] = (i < TT && j >= 0) ? Sp[i * TT + j] : 0.f;
        }
#pragma unroll
        for (int p = 0; p < SPF; p++) {
            int i = ib + SPF + p;
            if (i >= d) {
                float a = bufB[p];
                s += a;
                m = fmaxf(m, s * (1.f - a));
                Sp[i * TT + (i - d)] = s - m;
            }
        }
    }
}

// ---------------------------------------------------------------------------
// K5: fused causal softmax((scan + j/(i+1))/tau) + P@V, flash style.
// One block per (i-tile of 64 rows, bh). Online max/sum in registers,
// accumulator rescaling. Reads S exactly once; writes O only.
// grid (16, 32), block 256. All smem rows stride 68 floats = 272 B (16B-aligned).
// ---------------------------------------------------------------------------
__global__ __launch_bounds__(256) void k_pvsm() {
    int it = blockIdx.x, bh = blockIdx.y;
    int b = bh >> 3, h = bh & 7;
    const float* Sp = &g_S[bh][0][0];
    const float* V = &g_qkv[2][b * TT][h * DH];
    __shared__ float Ss[64][68];   // logits tile [row][j]
    __shared__ float Vs[64][68];   // V tile [j][d]
    __shared__ float Ps[64][68];   // probs [row][j]
    int tid = threadIdx.x;
    int tx = tid & 15, ty = tid >> 4;
    int i0 = it * 64;

    float acc[4][4], m[4], ssum[4], invi[4];
#pragma unroll
    for (int r = 0; r < 4; r++) {
        m[r] = -1e30f; ssum[r] = 0.f;
        invi[r] = 1.f / (float)(i0 + ty * 4 + r + 1);
#pragma unroll
        for (int c = 0; c < 4; c++) acc[r][c] = 0.f;
    }

    for (int jt = 0; jt <= it; jt++) {
        int j0 = jt * 64;
#pragma unroll
        for (int l = 0; l < 4; l++) {
            int row = ty + l * 16;
            *(float4*)&Ss[row][tx * 4] = *(const float4*)&Sp[(i0 + row) * TT + j0 + tx * 4];
            *(float4*)&Vs[row][tx * 4] = *(const float4*)&V[(j0 + row) * DDIM + tx * 4];
        }
        __syncthreads();

        // per-row online softmax over this thread's 4 columns, 16-lane reduce
#pragma unroll
        for (int r = 0; r < 4; r++) {
            int gi = i0 + ty * 4 + r;
            float4 s4 = *(float4*)&Ss[ty * 4 + r][tx * 4];
            float pr[4];
            int jb = j0 + tx * 4;
            pr[0] = (jb + 0 <= gi) ? s4.x + (float)(jb + 0) * invi[r] : -1e30f;
            pr[1] = (jb + 1 <= gi) ? s4.y + (float)(jb + 1) * invi[r] : -1e30f;
            pr[2] = (jb + 2 <= gi) ? s4.z + (float)(jb + 2) * invi[r] : -1e30f;
            pr[3] = (jb + 3 <= gi) ? s4.w + (float)(jb + 3) * invi[r] : -1e30f;
            float lmx = fmaxf(fmaxf(pr[0], pr[1]), fmaxf(pr[2], pr[3]));
#pragma unroll
            for (int o = 8; o > 0; o >>= 1)
                lmx = fmaxf(lmx, __shfl_xor_sync(0xffffffffu, lmx, o));
            float nm = fmaxf(m[r], lmx);
            float scale = __expf((m[r] - nm) * INV_TAU);
            m[r] = nm;
            float ts = 0.f;
#pragma unroll
            for (int c = 0; c < 4; c++) {
                float e = __expf((pr[c] - nm) * INV_TAU);
                pr[c] = e;
                ts += e;
            }
#pragma unroll
            for (int o = 8; o > 0; o >>= 1)
                ts += __shfl_xor_sync(0xffffffffu, ts, o);
            ssum[r] = ssum[r] * scale + ts;
#pragma unroll
            for (int c = 0; c < 4; c++) acc[r][c] *= scale;
            float4 p4 = {pr[0], pr[1], pr[2], pr[3]};
            *(float4*)&Ps[ty * 4 + r][tx * 4] = p4;
        }
        __syncthreads();

        // MAC: acc[r][c] += sum_k Ps[row][k] * Vs[k][col]
#pragma unroll 8
        for (int k4 = 0; k4 < 64; k4 += 4) {
            float4 a0 = *(float4*)&Ps[ty * 4 + 0][k4];
            float4 a1 = *(float4*)&Ps[ty * 4 + 1][k4];
            float4 a2 = *(float4*)&Ps[ty * 4 + 2][k4];
            float4 a3 = *(float4*)&Ps[ty * 4 + 3][k4];
            float4 b0 = *(float4*)&Vs[k4 + 0][tx * 4];
            float4 b1 = *(float4*)&Vs[k4 + 1][tx * 4];
            float4 b2 = *(float4*)&Vs[k4 + 2][tx * 4];
            float4 b3 = *(float4*)&Vs[k4 + 3][tx * 4];
            float ar[4][4] = {{a0.x, a0.y, a0.z, a0.w},
                              {a1.x, a1.y, a1.z, a1.w},
                              {a2.x, a2.y, a2.z, a2.w},
                              {a3.x, a3.y, a3.z, a3.w}};
            float bb[4][4] = {{b0.x, b0.y, b0.z, b0.w},
                              {b1.x, b1.y, b1.z, b1.w},
                              {b2.x, b2.y, b2.z, b2.w},
                              {b3.x, b3.y, b3.z, b3.w}};
#pragma unroll
            for (int r = 0; r < 4; r++)
#pragma unroll
                for (int kk = 0; kk < 4; kk++)
#pragma unroll
                    for (int c = 0; c < 4; c++)
                        acc[r][c] += ar[r][kk] * bb[kk][c];
        }
        __syncthreads();
    }
#pragma unroll
    for (int r = 0; r < 4; r++) {
        float inv = 1.f / ssum[r];
        float4 o4 = {acc[r][0] * inv, acc[r][1] * inv, acc[r][2] * inv, acc[r][3] * inv};
        *(float4*)&g_O[bh][i0 + ty * 4 + r][tx * 4] = o4;
    }
}

// ---------------------------------------------------------------------------
// K7: out[b,t,h*64+e] = sum_d O[bh][t][d] * wo[h*64+d][e]. K=64, N=64.
// grid (16, 32), block 256.
// ---------------------------------------------------------------------------
__global__ __launch_bounds__(256) void k_out(const float* __restrict__ wo,
                                             float* __restrict__ out) {
    int it = blockIdx.x, bh = blockIdx.y;
    int b = bh >> 3, h = bh & 7;
    __shared__ float Os[DH][68];
    __shared__ float Ws[DH][68];
    int tid = threadIdx.x;
    int lrow = tid >> 4, lcol = (tid & 15) * 4;
#pragma unroll
    for (int l = 0; l < 4; l++) {
        int row = lrow + l * 16;
        float4 o4 = *(const float4*)&g_O[bh][it * 64 + row][lcol];
        Os[lcol + 0][row] = o4.x; Os[lcol + 1][row] = o4.y;
        Os[lcol + 2][row] = o4.z; Os[lcol + 3][row] = o4.w;
        float4 w4 = *(const float4*)&wo[(h * 64 + row) * 64 + lcol];
        *(float4*)&Ws[row][lcol] = w4;
    }
    __syncthreads();
    int tx = tid & 15, ty = tid >> 4;
    float acc[4][4];
#pragma unroll
    for (int r = 0; r < 4; r++)
#pragma unroll
        for (int c = 0; c < 4; c++) acc[r][c] = 0.f;
#pragma unroll 8
    for (int k = 0; k < 64; k++) {
        float4 a4 = *(const float4*)&Os[k][ty * 4];
        float4 b4 = *(const float4*)&Ws[k][tx * 4];
        float a[4] = {a4.x, a4.y, a4.z, a4.w};
        float bb[4] = {b4.x, b4.y, b4.z, b4.w};
#pragma unroll
        for (int r = 0; r < 4; r++)
#pragma unroll
            for (int c = 0; c < 4; c++) acc[r][c] += a[r] * bb[c];
    }
#pragma unroll
    for (int r = 0; r < 4; r++) {
        int t = it * 64 + ty * 4 + r;
        float4 o4 = {acc[r][0], acc[r][1], acc[r][2], acc[r][3]};
        *(float4*)&out[(b * TT + t) * DDIM + h * 64 + tx * 4] = o4;
    }
}

// ---------------------------------------------------------------------------
extern "C" void kernel_launch(void* const* d_in, const int* in_sizes, int n_in,
                              void* d_out, int out_size) {
    const float* x  = (const float*)d_in[0];
    const float* wq = (const float*)d_in[1];
    const float* wk = (const float*)d_in[2];
    const float* wv = (const float*)d_in[3];
    const float* wo = (const float*)d_in[4];
    float* out = (float*)d_out;

    k_qkv<<<dim3(4, 32, 3), 256>>>(x, wq, wk, wv);
    k_sm64<<<12288, 256>>>();
    k_score<<<dim3(16, 16, 32), 256>>>();
    k_scan<<<dim3(8, 32), 128>>>();
    k_pvsm<<<dim3(16, 32), 256>>>();
    k_out<<<dim3(16, 32), 256>>>(wo, out);
}

// round 5
// speedup vs baseline: 1.3962x; 1.0570x over previous
#include <cuda_runtime.h>

// Fixed problem shapes
#define BSZ  4
#define TT   1024
#define DDIM 512
#define HH   8
#define DH   64
#define MROWS (BSZ*TT)   // 4096
#define NBH   (BSZ*HH)   // 32
#define INV_TAU 10.0f

// Scratch (device globals: allocation-free)
__device__ __align__(128) float g_qkv[3][MROWS][DDIM];   // 25 MB: q,k,v post-softmax
__device__ __align__(128) float g_S[NBH][TT][TT];        // 134 MB: scores -> scan
__device__ __align__(128) float g_O[NBH][TT][DH];        // 8 MB: attention output

// ---------------------------------------------------------------------------
// K1: QKV projections WITH fused per-head softmax(x/tau) epilogue.
// 128x128 tile, BK=8, 8x8 per thread, 256 threads. grid (4, 32, 3).
// Thread (tx,ty): rows ty*8..+7, cols tx*8..+7. A 64-col head spans tx 0..7
// or 8..15; those 8 threads sit in one 8-lane shfl group (lane=(ty&1)*16+tx),
// so xor-offsets 4,2,1 reduce exactly over the head.
// ---------------------------------------------------------------------------
__global__ __launch_bounds__(256) void k_qkv(const float* __restrict__ X,
                                             const float* __restrict__ Wq,
                                             const float* __restrict__ Wk,
                                             const float* __restrict__ Wv) {
    const float* W = (blockIdx.z == 0) ? Wq : ((blockIdx.z == 1) ? Wk : Wv);
    float* Out = &g_qkv[blockIdx.z][0][0];
    __shared__ float As[8][128];
    __shared__ float Bs[8][128];
    int tid = threadIdx.x;
    int m0 = blockIdx.y * 128, n0 = blockIdx.x * 128;
    int arow = tid >> 1, acol = (tid & 1) * 4;
    int brow = tid >> 5, bcol = (tid & 31) * 4;
    int tx = tid & 15, ty = tid >> 4;
    float acc[8][8];
#pragma unroll
    for (int r = 0; r < 8; r++)
#pragma unroll
        for (int c = 0; c < 8; c++) acc[r][c] = 0.f;

    for (int k0 = 0; k0 < DDIM; k0 += 8) {
        float4 av = *(const float4*)&X[(m0 + arow) * DDIM + k0 + acol];
        float4 bv = *(const float4*)&W[(k0 + brow) * DDIM + n0 + bcol];
        __syncthreads();
        As[acol + 0][arow] = av.x; As[acol + 1][arow] = av.y;
        As[acol + 2][arow] = av.z; As[acol + 3][arow] = av.w;
        *(float4*)&Bs[brow][bcol] = bv;
        __syncthreads();
#pragma unroll
        for (int k = 0; k < 8; k++) {
            float a[8], b[8];
            *(float4*)&a[0] = *(const float4*)&As[k][ty * 8];
            *(float4*)&a[4] = *(const float4*)&As[k][ty * 8 + 4];
            *(float4*)&b[0] = *(const float4*)&Bs[k][tx * 8];
            *(float4*)&b[4] = *(const float4*)&Bs[k][tx * 8 + 4];
#pragma unroll
            for (int r = 0; r < 8; r++)
#pragma unroll
                for (int c = 0; c < 8; c++) acc[r][c] += a[r] * b[c];
        }
    }
    // fused softmax over each head's 64 cols (8 cols local x 8 lanes)
#pragma unroll
    for (int r = 0; r < 8; r++) {
        float mx = acc[r][0];
#pragma unroll
        for (int c = 1; c < 8; c++) mx = fmaxf(mx, acc[r][c]);
#pragma unroll
        for (int o = 4; o > 0; o >>= 1) mx = fmaxf(mx, __shfl_xor_sync(0xffffffffu, mx, o));
        float s = 0.f;
#pragma unroll
        for (int c = 0; c < 8; c++) {
            acc[r][c] = __expf((acc[r][c] - mx) * INV_TAU);
            s += acc[r][c];
        }
#pragma unroll
        for (int o = 4; o > 0; o >>= 1) s += __shfl_xor_sync(0xffffffffu, s, o);
        float inv = 1.f / s;
#pragma unroll
        for (int c = 0; c < 8; c++) acc[r][c] *= inv;
    }
#pragma unroll
    for (int r = 0; r < 8; r++) {
        int row = m0 + ty * 8 + r;
        *(float4*)&Out[row * DDIM + n0 + tx * 8]     = *(float4*)&acc[r][0];
        *(float4*)&Out[row * DDIM + n0 + tx * 8 + 4] = *(float4*)&acc[r][4];
    }
}

// ---------------------------------------------------------------------------
// K3: S[bh][i][j] = q_sm[i]·k_sm[j], causal 128x128 tiles, BK=32, 8x8/thread.
// grid (8, 8, 32), block 256. Values above the diagonal inside diagonal
// tiles are garbage-but-finite; downstream only reads j<=i (scan) or masks
// (pvsm).
// ---------------------------------------------------------------------------
__global__ __launch_bounds__(256) void k_score() {
    int jt = blockIdx.x, it = blockIdx.y, bh = blockIdx.z;
    if (jt > it) return;
    int b = bh >> 3, h = bh & 7;
    const float* Q  = &g_qkv[0][b * TT][h * DH];
    const float* Kp = &g_qkv[1][b * TT][h * DH];
    __shared__ float Qs[32][132];
    __shared__ float Ks[32][132];
    int tid = threadIdx.x;
    int tx = tid & 15, ty = tid >> 4;
    float acc[8][8];
#pragma unroll
    for (int r = 0; r < 8; r++)
#pragma unroll
        for (int c = 0; c < 8; c++) acc[r][c] = 0.f;

    for (int k0 = 0; k0 < DH; k0 += 32) {
        __syncthreads();
#pragma unroll
        for (int l = 0; l < 4; l++) {
            int idx = tid + l * 256;
            int row = idx >> 3, cg = (idx & 7) * 4;
            float4 q4 = *(const float4*)&Q[(it * 128 + row) * DDIM + k0 + cg];
            float4 k4 = *(const float4*)&Kp[(jt * 128 + row) * DDIM + k0 + cg];
            Qs[cg + 0][row] = q4.x; Qs[cg + 1][row] = q4.y;
            Qs[cg + 2][row] = q4.z; Qs[cg + 3][row] = q4.w;
            Ks[cg + 0][row] = k4.x; Ks[cg + 1][row] = k4.y;
            Ks[cg + 2][row] = k4.z; Ks[cg + 3][row] = k4.w;
        }
        __syncthreads();
#pragma unroll
        for (int k = 0; k < 32; k++) {
            float a[8], bb[8];
            *(float4*)&a[0]  = *(const float4*)&Qs[k][ty * 8];
            *(float4*)&a[4]  = *(const float4*)&Qs[k][ty * 8 + 4];
            *(float4*)&bb[0] = *(const float4*)&Ks[k][tx * 8];
            *(float4*)&bb[4] = *(const float4*)&Ks[k][tx * 8 + 4];
#pragma unroll
            for (int r = 0; r < 8; r++)
#pragma unroll
                for (int c = 0; c < 8; c++) acc[r][c] += a[r] * bb[c];
        }
    }
    float* Sp = &g_S[bh][0][0];
#pragma unroll
    for (int r = 0; r < 8; r++) {
        int row = it * 128 + ty * 8 + r;
        *(float4*)&Sp[row * TT + jt * 128 + tx * 8]     = *(float4*)&acc[r][0];
        *(float4*)&Sp[row * TT + jt * 128 + tx * 8 + 4] = *(float4*)&acc[r][4];
    }
}

// ---------------------------------------------------------------------------
// K4: per-subdiagonal scan, in place on g_S. Thread t owns diagonal d.
// A/B double-buffered 32-row blocks: 32 loads in flight per thread.
// grid (8, 32), block 128.
// ---------------------------------------------------------------------------
#define SPF 32
__global__ __launch_bounds__(128) void k_scan() {
    int bh = blockIdx.y;
    int dbase = blockIdx.x * 128;
    int d = dbase + threadIdx.x;
    float* Sp = &g_S[bh][0][0];
    float bufA[SPF], bufB[SPF];
    float s = 0.f, m = 0.f;
#pragma unroll
    for (int p = 0; p < SPF; p++) {
        int i = dbase + p, j = i - d;
        bufA[p] = (j >= 0) ? Sp[i * TT + j] : 0.f;
    }
    for (int ib = dbase; ib < TT; ib += 2 * SPF) {
#pragma unroll
        for (int p = 0; p < SPF; p++) {
            int i = ib + SPF + p, j = i - d;
            bufB[p] = (i < TT && j >= 0) ? Sp[i * TT + j] : 0.f;
        }
#pragma unroll
        for (int p = 0; p < SPF; p++) {
            int i = ib + p;
            if (i >= d && i < TT) {
                float a = bufA[p];
                s += a;
                m = fmaxf(m, s * (1.f - a));
                Sp[i * TT + (i - d)] = s - m;
            }
        }
#pragma unroll
        for (int p = 0; p < SPF; p++) {
            int i = ib + 2 * SPF + p, j = i - d;
            bufA[p] = (i < TT && j >= 0) ? Sp[i * TT + j] : 0.f;
        }
#pragma unroll
        for (int p = 0; p < SPF; p++) {
            int i = ib + SPF + p;
            if (i >= d && i < TT) {
                float a = bufB[p];
                s += a;
                m = fmaxf(m, s * (1.f - a));
                Sp[i * TT + (i - d)] = s - m;
            }
        }
    }
}

// ---------------------------------------------------------------------------
// K5: fused causal softmax((scan + j/(i+1))/tau) + P@V, flash style.
// grid (16, 32), block 256. All smem rows stride 68 floats (16B-aligned).
// ---------------------------------------------------------------------------
__global__ __launch_bounds__(256) void k_pvsm() {
    int it = blockIdx.x, bh = blockIdx.y;
    int b = bh >> 3, h = bh & 7;
    const float* Sp = &g_S[bh][0][0];
    const float* V = &g_qkv[2][b * TT][h * DH];
    __shared__ float Ss[64][68];   // logits tile [row][j]
    __shared__ float Vs[64][68];   // V tile [j][d]
    __shared__ float Ps[64][68];   // probs [row][j]
    int tid = threadIdx.x;
    int tx = tid & 15, ty = tid >> 4;
    int i0 = it * 64;

    float acc[4][4], m[4], ssum[4], invi[4];
#pragma unroll
    for (int r = 0; r < 4; r++) {
        m[r] = -1e30f; ssum[r] = 0.f;
        invi[r] = 1.f / (float)(i0 + ty * 4 + r + 1);
#pragma unroll
        for (int c = 0; c < 4; c++) acc[r][c] = 0.f;
    }

    for (int jt = 0; jt <= it; jt++) {
        int j0 = jt * 64;
#pragma unroll
        for (int l = 0; l < 4; l++) {
            int row = ty + l * 16;
            *(float4*)&Ss[row][tx * 4] = *(const float4*)&Sp[(i0 + row) * TT + j0 + tx * 4];
            *(float4*)&Vs[row][tx * 4] = *(const float4*)&V[(j0 + row) * DDIM + tx * 4];
        }
        __syncthreads();

#pragma unroll
        for (int r = 0; r < 4; r++) {
            int gi = i0 + ty * 4 + r;
            float4 s4 = *(float4*)&Ss[ty * 4 + r][tx * 4];
            float pr[4];
            int jb = j0 + tx * 4;
            pr[0] = (jb + 0 <= gi) ? s4.x + (float)(jb + 0) * invi[r] : -1e30f;
            pr[1] = (jb + 1 <= gi) ? s4.y + (float)(jb + 1) * invi[r] : -1e30f;
            pr[2] = (jb + 2 <= gi) ? s4.z + (float)(jb + 2) * invi[r] : -1e30f;
            pr[3] = (jb + 3 <= gi) ? s4.w + (float)(jb + 3) * invi[r] : -1e30f;
            float lmx = fmaxf(fmaxf(pr[0], pr[1]), fmaxf(pr[2], pr[3]));
#pragma unroll
            for (int o = 8; o > 0; o >>= 1)
                lmx = fmaxf(lmx, __shfl_xor_sync(0xffffffffu, lmx, o));
            float nm = fmaxf(m[r], lmx);
            float scale = __expf((m[r] - nm) * INV_TAU);
            m[r] = nm;
            float ts = 0.f;
#pragma unroll
            for (int c = 0; c < 4; c++) {
                float e = __expf((pr[c] - nm) * INV_TAU);
                pr[c] = e;
                ts += e;
            }
#pragma unroll
            for (int o = 8; o > 0; o >>= 1)
                ts += __shfl_xor_sync(0xffffffffu, ts, o);
            ssum[r] = ssum[r] * scale + ts;
#pragma unroll
            for (int c = 0; c < 4; c++) acc[r][c] *= scale;
            float4 p4 = {pr[0], pr[1], pr[2], pr[3]};
            *(float4*)&Ps[ty * 4 + r][tx * 4] = p4;
        }
        __syncthreads();

#pragma unroll 8
        for (int k4 = 0; k4 < 64; k4 += 4) {
            float4 a0 = *(float4*)&Ps[ty * 4 + 0][k4];
            float4 a1 = *(float4*)&Ps[ty * 4 + 1][k4];
            float4 a2 = *(float4*)&Ps[ty * 4 + 2][k4];
            float4 a3 = *(float4*)&Ps[ty * 4 + 3][k4];
            float4 b0 = *(float4*)&Vs[k4 + 0][tx * 4];
            float4 b1 = *(float4*)&Vs[k4 + 1][tx * 4];
            float4 b2 = *(float4*)&Vs[k4 + 2][tx * 4];
            float4 b3 = *(float4*)&Vs[k4 + 3][tx * 4];
            float ar[4][4] = {{a0.x, a0.y, a0.z, a0.w},
                              {a1.x, a1.y, a1.z, a1.w},
                              {a2.x, a2.y, a2.z, a2.w},
                              {a3.x, a3.y, a3.z, a3.w}};
            float bb[4][4] = {{b0.x, b0.y, b0.z, b0.w},
                              {b1.x, b1.y, b1.z, b1.w},
                              {b2.x, b2.y, b2.z, b2.w},
                              {b3.x, b3.y, b3.z, b3.w}};
#pragma unroll
            for (int r = 0; r < 4; r++)
#pragma unroll
                for (int kk = 0; kk < 4; kk++)
#pragma unroll
                    for (int c = 0; c < 4; c++)
                        acc[r][c] += ar[r][kk] * bb[kk][c];
        }
        __syncthreads();
    }
#pragma unroll
    for (int r = 0; r < 4; r++) {
        float inv = 1.f / ssum[r];
        float4 o4 = {acc[r][0] * inv, acc[r][1] * inv, acc[r][2] * inv, acc[r][3] * inv};
        *(float4*)&g_O[bh][i0 + ty * 4 + r][tx * 4] = o4;
    }
}

// ---------------------------------------------------------------------------
// K7: out[b,t,h*64+e] = sum_d O[bh][t][d] * wo[h*64+d][e]. K=64, N=64.
// grid (16, 32), block 256.
// ---------------------------------------------------------------------------
__global__ __launch_bounds__(256) void k_out(const float* __restrict__ wo,
                                             float* __restrict__ out) {
    int it = blockIdx.x, bh = blockIdx.y;
    int b = bh >> 3, h = bh & 7;
    __shared__ float Os[DH][68];
    __shared__ float Ws[DH][68];
    int tid = threadIdx.x;
    int lrow = tid >> 4, lcol = (tid & 15) * 4;
#pragma unroll
    for (int l = 0; l < 4; l++) {
        int row = lrow + l * 16;
        float4 o4 = *(const float4*)&g_O[bh][it * 64 + row][lcol];
        Os[lcol + 0][row] = o4.x; Os[lcol + 1][row] = o4.y;
        Os[lcol + 2][row] = o4.z; Os[lcol + 3][row] = o4.w;
        float4 w4 = *(const float4*)&wo[(h * 64 + row) * 64 + lcol];
        *(float4*)&Ws[row][lcol] = w4;
    }
    __syncthreads();
    int tx = tid & 15, ty = tid >> 4;
    float acc[4][4];
#pragma unroll
    for (int r = 0; r < 4; r++)
#pragma unroll
        for (int c = 0; c < 4; c++) acc[r][c] = 0.f;
#pragma unroll 8
    for (int k = 0; k < 64; k++) {
        float4 a4 = *(const float4*)&Os[k][ty * 4];
        float4 b4 = *(const float4*)&Ws[k][tx * 4];
        float a[4] = {a4.x, a4.y, a4.z, a4.w};
        float bb[4] = {b4.x, b4.y, b4.z, b4.w};
#pragma unroll
        for (int r = 0; r < 4; r++)
#pragma unroll
            for (int c = 0; c < 4; c++) acc[r][c] += a[r] * bb[c];
    }
#pragma unroll
    for (int r = 0; r < 4; r++) {
        int t = it * 64 + ty * 4 + r;
        float4 o4 = {acc[r][0], acc[r][1], acc[r][2], acc[r][3]};
        *(float4*)&out[(b * TT + t) * DDIM + h * 64 + tx * 4] = o4;
    }
}

// ---------------------------------------------------------------------------
extern "C" void kernel_launch(void* const* d_in, const int* in_sizes, int n_in,
                              void* d_out, int out_size) {
    const float* x  = (const float*)d_in[0];
    const float* wq = (const float*)d_in[1];
    const float* wk = (const float*)d_in[2];
    const float* wv = (const float*)d_in[3];
    const float* wo = (const float*)d_in[4];
    float* out = (float*)d_out;

    k_qkv<<<dim3(4, 32, 3), 256>>>(x, wq, wk, wv);
    k_score<<<dim3(8, 8, 32), 256>>>();
    k_scan<<<dim3(8, 32), 128>>>();
    k_pvsm<<<dim3(16, 32), 256>>>();
    k_out<<<dim3(16, 32), 256>>>(wo, out);
}